// round 12
// baseline (speedup 1.0000x reference)
#include <cuda_runtime.h>
#include <stdint.h>

#define N_NODES 50000
#define N_EDGES 625000
#define D 128
#define DQ 32            // D / 4 (float4s per row)
#define K2 256           // 2*D

// ---------------- scratch (device globals; no cudaMalloc allowed) ----------
__device__ int    g_is64;                            // 1 if indices are int64
__device__ int    g_outdeg[N_NODES];
__device__ int    g_indeg[N_NODES];
__device__ float  g_scaleR[N_NODES];                 // (1/outdeg)*rsqrt(indeg)
__device__ float4 g_scaled[(size_t)N_NODES * DQ];    // x * rsqrt(outdeg)
__device__ float4 g_aggn[(size_t)N_NODES * DQ];      // normalized aggregate
__device__ int    g_off[N_NODES + 1];                // CSR offsets (by receiver)
__device__ int    g_cursor[N_NODES];                 // fill cursors
__device__ int    g_esrc[N_EDGES];                   // edge sources grouped by recv
__device__ float  g_Wt[K2 * D];                      // W^T: Wt[k][n] = W[n][k]

// ---------------- index decode --------------------------------------------
__device__ __forceinline__ int load_idx(const void* p, int e, int is64) {
    long long v = is64 ? ((const long long*)p)[e]
                       : (long long)((const int*)p)[e];
    // defensive clamp: wrong decode -> finite wrong answer, never a trap
    if (v < 0) v = 0;
    if (v >= N_NODES) v = N_NODES - 1;
    return (int)v;
}

// ---------------- kernel 0: detect index dtype -----------------------------
__global__ void k_detect(const void* snd) {
    if (threadIdx.x == 0) {
        const long long* p = (const long long*)snd;
        int is64 = 1;
        for (int i = 0; i < 16; i++) {
            long long v = p[i];
            if (v < 0 || v >= (long long)N_NODES) { is64 = 0; break; }
        }
        g_is64 = is64;
    }
}

// ---------------- kernel 1: init degrees to 1 (self loops) -----------------
__global__ void k_init_deg() {
    int i = blockIdx.x * blockDim.x + threadIdx.x;
    if (i < N_NODES) { g_outdeg[i] = 1; g_indeg[i] = 1; }
}

// ---------------- kernel 2: count degrees (int atomics only) ---------------
__global__ void k_count(const void* __restrict__ snd,
                        const void* __restrict__ rcv) {
    int e = blockIdx.x * blockDim.x + threadIdx.x;
    if (e >= N_EDGES) return;
    int is64 = g_is64;
    int s = load_idx(snd, e, is64);
    int r = load_idx(rcv, e, is64);
    atomicAdd(&g_outdeg[r], 1);   // out_degree counted over receivers
    atomicAdd(&g_indeg[s], 1);    // in_degree counted over senders
}

// ---------------- kernel 3: exclusive scan of (outdeg-1) -> CSR offsets ----
// Single block, 1024 threads, warp-shuffle scan over 49 chunks.
__global__ void k_scan() {
    __shared__ int warp_excl[32];
    __shared__ int s_carry;
    int lane = threadIdx.x & 31, wid = threadIdx.x >> 5;
    if (threadIdx.x == 0) s_carry = 0;
    __syncthreads();
    for (int base = 0; base < N_NODES; base += 1024) {
        int i = base + threadIdx.x;
        int v = (i < N_NODES) ? (g_outdeg[i] - 1) : 0;   // incoming edge count
        int incl = v;
#pragma unroll
        for (int off = 1; off < 32; off <<= 1) {
            int t = __shfl_up_sync(0xffffffffu, incl, off);
            if (lane >= off) incl += t;
        }
        if (lane == 31) warp_excl[wid] = incl;           // warp totals
        __syncthreads();
        if (wid == 0) {
            int ws = warp_excl[lane];
            int wincl = ws;
#pragma unroll
            for (int off = 1; off < 32; off <<= 1) {
                int t = __shfl_up_sync(0xffffffffu, wincl, off);
                if (lane >= off) wincl += t;
            }
            warp_excl[lane] = wincl - ws;                // exclusive warp prefix
        }
        __syncthreads();
        int excl = (incl - v) + warp_excl[wid] + s_carry;
        if (i < N_NODES) { g_off[i] = excl; g_cursor[i] = excl; }
        __syncthreads();                                  // protect warp_excl reuse
        if (threadIdx.x == 1023) s_carry = excl + v;      // chunk total
        __syncthreads();
    }
    if (threadIdx.x == 0) g_off[N_NODES] = s_carry;       // == N_EDGES
}

// ---------------- kernel 4: bucket edge sources by receiver ----------------
__global__ void k_fill(const void* __restrict__ snd,
                       const void* __restrict__ rcv) {
    int e = blockIdx.x * blockDim.x + threadIdx.x;
    if (e >= N_EDGES) return;
    int is64 = g_is64;
    int s = load_idx(snd, e, is64);
    int r = load_idx(rcv, e, is64);
    int pos = atomicAdd(&g_cursor[r], 1);
    if (pos >= 0 && pos < N_EDGES) g_esrc[pos] = s;
}

// ---------------- kernel 5: scaled = x * rsqrt(outdeg); scaleR -------------
__global__ void k_prep(const float* __restrict__ x) {
    int idx = blockIdx.x * blockDim.x + threadIdx.x;   // N_NODES * DQ float4s
    if (idx >= N_NODES * DQ) return;
    int row  = idx >> 5;
    int quad = idx & 31;
    float od  = (float)g_outdeg[row];
    float odn = rsqrtf(od);
    float4 v = ((const float4*)(x + (size_t)row * D))[quad];
    v.x *= odn; v.y *= odn; v.z *= odn; v.w *= odn;
    g_scaled[(size_t)row * DQ + quad] = v;
    if (quad == 0) {
        float in_d = (float)g_indeg[row];
        g_scaleR[row] = (1.0f / od) * rsqrtf(in_d);
    }
}

// ---------------- kernel 6: gather + normalize (warp per node) -------------
// aggn[i] = ( scaled[i] + sum_{e: recv(e)=i} scaled[src(e)] ) * scaleR[i]
__global__ void k_gather() {
    int node = blockIdx.x * 8 + (threadIdx.x >> 5);
    if (node >= N_NODES) return;
    int lane = threadIdx.x & 31;
    int beg = __ldg(&g_off[node]);
    int end = __ldg(&g_off[node + 1]);
    float4 acc = g_scaled[(size_t)node * DQ + lane];     // self loop
    int p = beg;
    for (; p + 2 <= end; p += 2) {                       // 2-way unroll for MLP
        int s0 = __ldg(&g_esrc[p]);
        int s1 = __ldg(&g_esrc[p + 1]);
        float4 v0 = g_scaled[(size_t)s0 * DQ + lane];
        float4 v1 = g_scaled[(size_t)s1 * DQ + lane];
        acc.x += v0.x; acc.y += v0.y; acc.z += v0.z; acc.w += v0.w;
        acc.x += v1.x; acc.y += v1.y; acc.z += v1.z; acc.w += v1.w;
    }
    if (p < end) {
        int s0 = __ldg(&g_esrc[p]);
        float4 v0 = g_scaled[(size_t)s0 * DQ + lane];
        acc.x += v0.x; acc.y += v0.y; acc.z += v0.z; acc.w += v0.w;
    }
    float sc = g_scaleR[node];
    acc.x *= sc; acc.y *= sc; acc.z *= sc; acc.w *= sc;
    g_aggn[(size_t)node * DQ + lane] = acc;
}

// ---------------- kernel 7: transpose W [D, 2D] -> Wt [2D, D] --------------
__global__ void k_transpose(const float* __restrict__ W) {
    int idx = blockIdx.x * blockDim.x + threadIdx.x;
    if (idx >= D * K2) return;
    int n = idx / K2;
    int k = idx % K2;
    g_Wt[k * D + n] = W[idx];
}

// ---------------- kernel 8: GEMM  out = [x | aggn] @ W^T + b ---------------
#define BM 128
#define BN 128
#define BK 32
__global__ __launch_bounds__(256, 2)
void k_gemm(const float* __restrict__ x, const float* __restrict__ bias,
            float* __restrict__ out) {
    __shared__ __align__(16) float As[BK][BM + 4];
    __shared__ __align__(16) float Bs[BK][BN];
    int tid = threadIdx.x;
    int row0 = blockIdx.x * BM;
    int tx = tid & 15;     // 8 output cols each
    int ty = tid >> 4;     // 8 output rows each
    float acc[8][8];
#pragma unroll
    for (int i = 0; i < 8; i++)
#pragma unroll
        for (int j = 0; j < 8; j++) acc[i][j] = 0.0f;

    for (int k0 = 0; k0 < K2; k0 += BK) {
        bool isAgg = (k0 >= D);
        int kbase = isAgg ? (k0 - D) : k0;
        // A tile: 128 rows x 32 k = 1024 float4s; 4 per thread
#pragma unroll
        for (int it = 0; it < 4; it++) {
            int slot = tid + it * 256;
            int r  = slot >> 3;
            int kv = slot & 7;
            int grow = row0 + r;
            float4 v = make_float4(0.f, 0.f, 0.f, 0.f);
            if (grow < N_NODES) {
                v = isAgg ? g_aggn[(size_t)grow * DQ + (kbase >> 2) + kv]
                          : *(const float4*)(x + (size_t)grow * D + kbase + kv * 4);
            }
            As[kv * 4 + 0][r] = v.x;
            As[kv * 4 + 1][r] = v.y;
            As[kv * 4 + 2][r] = v.z;
            As[kv * 4 + 3][r] = v.w;
        }
        // B tile: Wt rows k0..k0+31 x 128 cols
#pragma unroll
        for (int it = 0; it < 4; it++) {
            int slot = tid + it * 256;
            int kk = slot >> 5;
            int nv = slot & 31;
            *(float4*)(&Bs[kk][nv * 4]) =
                *(const float4*)(g_Wt + (size_t)(k0 + kk) * D + nv * 4);
        }
        __syncthreads();
#pragma unroll
        for (int kk = 0; kk < BK; kk++) {
            float4 a0 = *(const float4*)(&As[kk][ty * 8 + 0]);
            float4 a1 = *(const float4*)(&As[kk][ty * 8 + 4]);
            float4 b0 = *(const float4*)(&Bs[kk][tx * 8 + 0]);
            float4 b1 = *(const float4*)(&Bs[kk][tx * 8 + 4]);
            float ra[8] = {a0.x, a0.y, a0.z, a0.w, a1.x, a1.y, a1.z, a1.w};
            float rb[8] = {b0.x, b0.y, b0.z, b0.w, b1.x, b1.y, b1.z, b1.w};
#pragma unroll
            for (int i = 0; i < 8; i++)
#pragma unroll
                for (int j = 0; j < 8; j++)
                    acc[i][j] += ra[i] * rb[j];
        }
        __syncthreads();
    }
#pragma unroll
    for (int i = 0; i < 8; i++) {
        int grow = row0 + ty * 8 + i;
        if (grow >= N_NODES) continue;
#pragma unroll
        for (int j = 0; j < 8; j += 4) {
            int col = tx * 8 + j;
            float4 o;
            o.x = acc[i][j + 0] + bias[col + 0];
            o.y = acc[i][j + 1] + bias[col + 1];
            o.z = acc[i][j + 2] + bias[col + 2];
            o.w = acc[i][j + 3] + bias[col + 3];
            *(float4*)(out + (size_t)grow * D + col) = o;
        }
    }
}

// ---------------- launch ----------------------------------------------------
extern "C" void kernel_launch(void* const* d_in, const int* in_sizes, int n_in,
                              void* d_out, int out_size) {
    const float* x   = nullptr;
    const void*  snd = nullptr;
    const void*  rcv = nullptr;
    const float* W   = nullptr;
    const float* b   = nullptr;
    for (int i = 0; i < n_in; i++) {
        long long sz = in_sizes[i];
        if (sz == (long long)N_NODES * D)      x = (const float*)d_in[i];
        else if (sz == N_EDGES) { if (!snd) snd = d_in[i];
                                  else      rcv = d_in[i]; }
        else if (sz == (long long)D * K2)      W = (const float*)d_in[i];
        else if (sz == D)                      b = (const float*)d_in[i];
        // sz == 1 -> scalar n_nodes (compile-time constant here)
    }
    float* out = (float*)d_out;

    k_detect<<<1, 32>>>(snd);
    k_init_deg<<<(N_NODES + 255) / 256, 256>>>();
    k_count<<<(N_EDGES + 255) / 256, 256>>>(snd, rcv);
    k_scan<<<1, 1024>>>();
    k_fill<<<(N_EDGES + 255) / 256, 256>>>(snd, rcv);
    k_prep<<<(N_NODES * DQ + 255) / 256, 256>>>(x);
    k_gather<<<(N_NODES + 7) / 8, 256>>>();
    k_transpose<<<(D * K2 + 255) / 256, 256>>>(W);
    k_gemm<<<(N_NODES + BM - 1) / BM, 256>>>(x, b, out);
}